// round 12
// baseline (speedup 1.0000x reference)
#include <cuda_runtime.h>
#include <cuda_fp16.h>
#include <cstdint>

#define BB 4
#define NN 8192
#define HH 8
#define DD 64
#define BH 32
#define RS 512

#define P1_CHUNK 256
#define NCH (NN/P1_CHUNK)    // 32 chunks
#define T1 32
#define S1K 72
#define S1V 88

#define T2 128
#define S2H 72

__device__ float g_part[BH][NCH][72][DD];
__device__ __align__(16) __half g_KVh[BH][72][DD];
__device__ int g_cnt[BH];    // zero-initialized; each launch ends with it back at 0

__device__ __forceinline__ float elu1(float x) {
    return __expf(fminf(x, 0.f)) + fmaxf(x, 0.f);
}

__device__ __forceinline__ uint32_t smem_u32(const void* p) {
    uint32_t a;
    asm("{ .reg .u64 t; cvta.to.shared.u64 t, %1; cvt.u32.u64 %0, t; }" : "=r"(a) : "l"(p));
    return a;
}

__device__ __forceinline__ void mma16(float* c, const uint32_t* a, const uint32_t* b) {
    asm volatile(
        "mma.sync.aligned.m16n8k16.row.col.f32.f16.f16.f32 "
        "{%0,%1,%2,%3}, {%4,%5,%6,%7}, {%8,%9}, {%0,%1,%2,%3};"
        : "+f"(c[0]), "+f"(c[1]), "+f"(c[2]), "+f"(c[3])
        : "r"(a[0]), "r"(a[1]), "r"(a[2]), "r"(a[3]), "r"(b[0]), "r"(b[1]));
}

__device__ __forceinline__ void ldm_x4(uint32_t* r, uint32_t addr) {
    asm volatile("ldmatrix.sync.aligned.m8n8.x4.shared.b16 {%0,%1,%2,%3}, [%4];"
                 : "=r"(r[0]), "=r"(r[1]), "=r"(r[2]), "=r"(r[3]) : "r"(addr));
}
__device__ __forceinline__ void ldm_x4t(uint32_t* r, uint32_t addr) {
    asm volatile("ldmatrix.sync.aligned.m8n8.x4.trans.shared.b16 {%0,%1,%2,%3}, [%4];"
                 : "=r"(r[0]), "=r"(r[1]), "=r"(r[2]), "=r"(r[3]) : "r"(addr));
}
__device__ __forceinline__ void ldm_x2(uint32_t* r, uint32_t addr) {
    asm volatile("ldmatrix.sync.aligned.m8n8.x2.shared.b16 {%0,%1}, [%2];"
                 : "=r"(r[0]), "=r"(r[1]) : "r"(addr));
}
__device__ __forceinline__ void ldm_x2t(uint32_t* r, uint32_t addr) {
    asm volatile("ldmatrix.sync.aligned.m8n8.x2.trans.shared.b16 {%0,%1}, [%2];"
                 : "=r"(r[0]), "=r"(r[1]) : "r"(addr));
}

__device__ __forceinline__ void cp16(uint32_t dst, const void* src) {
    asm volatile("cp.async.cg.shared.global [%0], [%1], 16;" :: "r"(dst), "l"(src));
}
__device__ __forceinline__ void cp_commit() {
    asm volatile("cp.async.commit_group;" ::: "memory");
}
__device__ __forceinline__ void cp_wait1() {
    asm volatile("cp.async.wait_group 1;" ::: "memory");
}
__device__ __forceinline__ void cp_wait0() {
    asm volatile("cp.async.wait_group 0;" ::: "memory");
}

// ---------------------------------------------------------------------------
// Phase 1 (fp16 mma + cp.async pipeline + fused last-block reduction):
//   g_part[bh][chunk][m][d] = sum_n V'[n][m]*Kf[n][d]
//   last block per bh: g_KVh[bh] = (half) sum_chunks g_part[bh][chunk]
// grid (BH, NCH=32), block 320 (10 warps: mg = w>>1, dg = w&1)
// ---------------------------------------------------------------------------
__global__ __launch_bounds__(320, 4) void phase1_kernel(
    const float* __restrict__ Kg,
    const float* __restrict__ Vg,
    const float* __restrict__ maskg)
{
    __shared__ __align__(16) float KstF[2][T1][DD];
    __shared__ __align__(16) float VstF[2][T1][DD];
    __shared__ __half Ks[2][T1][S1K];
    __shared__ __half Vs[2][T1][S1V];
    __shared__ int isLast;

    const int bh = blockIdx.x, b = bh >> 3, h = bh & 7;
    const int chunk = blockIdx.y;
    const int t = threadIdx.x;
    const int w = t >> 5, lane = t & 31, q = lane & 3;
    const int g = lane >> 2, lr = lane & 7, sel = lane >> 3;
    const int mg = w >> 1, dg = w & 1;
    const int mrow = mg * 16;
    const int dcol = dg * 32;

    if (t < 64) {
        int bu = t >> 5, r = t & 31;
        Vs[bu][r][64] = __float2half(1.f);
        #pragma unroll
        for (int e = 65; e < 80; ++e) Vs[bu][r][e] = __float2half(0.f);
    }

    const size_t base = (size_t)b * NN * RS + (size_t)h * DD;
    const int n_beg = chunk * P1_CHUNK;
    const int NT = P1_CHUNK / T1;   // 8

    const bool loader = t < 256;
    const int r_ = (t & 255) >> 4, c_ = (t & 15) * 4;

    const float* kp = Kg + base + (size_t)(n_beg + r_) * RS + c_;
    const float* vp = Vg + base + (size_t)(n_beg + r_) * RS + c_;
    const float* mp = maskg + b * NN + n_beg + r_;

    const uint32_t kstb = smem_u32(&KstF[0][0][0]);
    const uint32_t vstb = smem_u32(&VstF[0][0][0]);

    const uint32_t ksb = smem_u32(&Ks[0][0][0]);
    const uint32_t vsb = smem_u32(&Vs[0][0][0]);
    const uint32_t aA = vsb + (((lr + (sel >> 1) * 8) * S1V) + mrow + (sel & 1) * 8) * 2;
    const uint32_t aB = ksb + (((lr + (sel & 1) * 8) * S1K) + dcol) * 2;
    const uint32_t BUFK = T1 * S1K * 2;
    const uint32_t BUFV = T1 * S1V * 2;

    float mreg[2][2];

    auto issue = [&](int tl, int s) {
        const int goff = tl * T1 * RS;
        if (loader) {
            const uint32_t d0 = kstb + ((s * T1 + r_) * DD + c_) * 4;
            const uint32_t d1 = vstb + ((s * T1 + r_) * DD + c_) * 4;
            cp16(d0,                kp + goff);
            cp16(d0 + 16 * DD * 4,  kp + goff + 16 * RS);
            cp16(d1,                vp + goff);
            cp16(d1 + 16 * DD * 4,  vp + goff + 16 * RS);
            mreg[s][0] = __ldg(mp + tl * T1);
            mreg[s][1] = __ldg(mp + tl * T1 + 16);
        }
    };

    float acc[4][4] = {};

    issue(0, 0); cp_commit();
    issue(1, 1); cp_commit();

    for (int tile = 0; tile < NT; ++tile) {
        const int s = tile & 1;
        cp_wait1();

        if (loader) {
            #pragma unroll
            for (int i = 0; i < 2; ++i) {
                int r = r_ + i * 16;
                float msk = mreg[s][i];
                float4 k4 = *(const float4*)&KstF[s][r][c_];
                float4 v4 = *(const float4*)&VstF[s][r][c_];
                *(__half2*)&Ks[s][r][c_]     = __floats2half2_rn(elu1(k4.x) * msk, elu1(k4.y) * msk);
                *(__half2*)&Ks[s][r][c_ + 2] = __floats2half2_rn(elu1(k4.z) * msk, elu1(k4.w) * msk);
                *(__half2*)&Vs[s][r][c_]     = __floats2half2_rn(v4.x, v4.y);
                *(__half2*)&Vs[s][r][c_ + 2] = __floats2half2_rn(v4.z, v4.w);
            }
        }
        __syncthreads();

        if (tile + 2 < NT) issue(tile + 2, s);
        cp_commit();

        #pragma unroll
        for (int kt = 0; kt < 2; ++kt) {
            uint32_t a[4];
            ldm_x4t(a, aA + s * BUFV + kt * 16 * S1V * 2);
            #pragma unroll
            for (int j = 0; j < 4; ++j) {
                uint32_t bf[2];
                ldm_x2t(bf, aB + s * BUFK + (kt * 16 * S1K + j * 8) * 2);
                mma16(acc[j], a, bf);
            }
        }
    }

    float* dst = &g_part[bh][chunk][0][0];
    #pragma unroll
    for (int j = 0; j < 4; ++j) {
        const int col = dcol + j * 8 + 2 * q;
        *(float2*)(dst + (mrow + g) * DD + col) = make_float2(acc[j][0], acc[j][1]);
        if (mg < 4)
            *(float2*)(dst + (mrow + 8 + g) * DD + col) = make_float2(acc[j][2], acc[j][3]);
    }

    // ---- fused reduction: last block per bh sums the 32 partials ----
    __threadfence();
    if (t == 0) {
        int v = atomicAdd(&g_cnt[bh], 1);
        isLast = (v == NCH - 1);
    }
    __syncthreads();
    if (isLast) {
        if (t == 0) g_cnt[bh] = 0;         // reset for next launch/replay
        for (int i = t; i < 72 * 32; i += 320) {
            int row = i >> 5, col = (i & 31) * 2;
            float sx = 0.f, sy = 0.f;
            #pragma unroll 8
            for (int c = 0; c < NCH; ++c) {
                float2 v2 = *(const float2*)&g_part[bh][c][row][col];
                sx += v2.x; sy += v2.y;
            }
            *(__half2*)&g_KVh[bh][row][col] = __floats2half2_rn(sx, sy);
        }
    }
}

// ---------------------------------------------------------------------------
// Phase 2 (fp16 mma): out[n,m] = (Qf[n,:].KV[m,:]) / (Qf[n,:].Ksum + eps)
// grid (BH, NN/T2=64), block 256; warp w: rows w*16..+15
// ---------------------------------------------------------------------------
__global__ __launch_bounds__(256) void phase2_kernel(
    const float* __restrict__ Qg,
    float* __restrict__ Og)
{
    __shared__ __half Qs[T2][S2H];
    __shared__ __align__(16) __half KVs[72][S2H];

    const int bh = blockIdx.x, b = bh >> 3, h = bh & 7;
    const int t = threadIdx.x;
    const int w = t >> 5, lane = t & 31, q = lane & 3;
    const int g = lane >> 2, lr = lane & 7, sel = lane >> 3;
    const int r0 = w * 16;

    const size_t base = (size_t)b * NN * RS + (size_t)h * DD;
    const int n0 = blockIdx.y * T2;

    float4 q4[8];
    {
        const float* src = Qg + base + (size_t)n0 * RS;
        #pragma unroll
        for (int i = 0; i < 8; ++i) {
            int idx = t + i * 256;
            int r = idx >> 4, c = (idx & 15) * 4;
            q4[i] = *(const float4*)(src + (size_t)r * RS + c);
        }
    }

    {
        const uint32_t kvb = smem_u32(&KVs[0][0]);
        const char* srcb = (const char*)&g_KVh[bh][0][0];
        for (int i = t; i < 72 * 8; i += 256) {
            int r = i >> 3, c = i & 7;
            cp16(kvb + (r * S2H + c * 8) * 2, srcb + (r * 64 + c * 8) * 2);
        }
        cp_commit();
    }

    #pragma unroll
    for (int i = 0; i < 8; ++i) {
        int idx = t + i * 256;
        int r = idx >> 4, c = (idx & 15) * 4;
        *(__half2*)&Qs[r][c]     = __floats2half2_rn(elu1(q4[i].x), elu1(q4[i].y));
        *(__half2*)&Qs[r][c + 2] = __floats2half2_rn(elu1(q4[i].z), elu1(q4[i].w));
    }
    cp_wait0();
    __syncthreads();

    const uint32_t qsb = smem_u32(&Qs[0][0]);
    const uint32_t kvb = smem_u32(&KVs[0][0]);

    uint32_t a[4][4];
    #pragma unroll
    for (int kt = 0; kt < 4; ++kt) {
        int row = r0 + lr + (sel & 1) * 8;
        int col = kt * 16 + (sel & 2) * 4;
        ldm_x4(a[kt], qsb + (row * S2H + col) * 2);
    }

    float dacc[4] = {};
    #pragma unroll
    for (int kt = 0; kt < 4; ++kt) {
        uint32_t bf[2];
        int row = 64 + lr;
        int col = kt * 16 + (sel & 1) * 8;
        ldm_x2(bf, kvb + (row * S2H + col) * 2);
        mma16(dacc, a[kt], bf);
    }
    const int src = lane & ~3;
    float den0 = __shfl_sync(0xffffffffu, dacc[0], src);
    float den1 = __shfl_sync(0xffffffffu, dacc[2], src);
    float z0 = 1.f / (den0 + 1e-6f);
    float z1 = 1.f / (den1 + 1e-6f);

    float* row_a = Og + base + (size_t)(n0 + r0 + g) * RS;
    float* row_b = row_a + 8 * RS;

    #pragma unroll
    for (int j = 0; j < 8; ++j) {
        float acc[4] = {};
        #pragma unroll
        for (int kt = 0; kt < 4; ++kt) {
            uint32_t bf[2];
            int row = j * 8 + lr;
            int col = kt * 16 + (sel & 1) * 8;
            ldm_x2(bf, kvb + (row * S2H + col) * 2);
            mma16(acc, a[kt], bf);
        }
        const int col = j * 8 + 2 * q;
        __stcs((float2*)(row_a + col), make_float2(acc[0] * z0, acc[1] * z0));
        __stcs((float2*)(row_b + col), make_float2(acc[2] * z1, acc[3] * z1));
    }
}

extern "C" void kernel_launch(void* const* d_in, const int* in_sizes, int n_in,
                              void* d_out, int out_size) {
    const float* Q    = (const float*)d_in[0];
    const float* K    = (const float*)d_in[1];
    const float* V    = (const float*)d_in[2];
    const float* mask = (const float*)d_in[3];
    float* out = (float*)d_out;

    dim3 g1(BH, NCH);
    phase1_kernel<<<g1, 320>>>(K, V, mask);

    dim3 g2(BH, NN / T2);
    phase2_kernel<<<g2, 256>>>(Q, out);
}

// round 13
// speedup vs baseline: 1.2512x; 1.2512x over previous
#include <cuda_runtime.h>
#include <cuda_fp16.h>
#include <cstdint>

#define BB 4
#define NN 8192
#define HH 8
#define DD 64
#define BH 32
#define RS 512

#define P1_CHUNK 256
#define NCH (NN/P1_CHUNK)    // 32 chunks
#define T1 32
#define S1K 72
#define S1V 88

#define T2 128
#define S2H 72

__device__ float g_part[BH][NCH][72][DD];
__device__ __align__(16) __half g_KVh[BH][72][DD];

__device__ __forceinline__ float elu1(float x) {
    return __expf(fminf(x, 0.f)) + fmaxf(x, 0.f);
}

__device__ __forceinline__ uint32_t smem_u32(const void* p) {
    uint32_t a;
    asm("{ .reg .u64 t; cvta.to.shared.u64 t, %1; cvt.u32.u64 %0, t; }" : "=r"(a) : "l"(p));
    return a;
}

__device__ __forceinline__ void mma16(float* c, const uint32_t* a, const uint32_t* b) {
    asm volatile(
        "mma.sync.aligned.m16n8k16.row.col.f32.f16.f16.f32 "
        "{%0,%1,%2,%3}, {%4,%5,%6,%7}, {%8,%9}, {%0,%1,%2,%3};"
        : "+f"(c[0]), "+f"(c[1]), "+f"(c[2]), "+f"(c[3])
        : "r"(a[0]), "r"(a[1]), "r"(a[2]), "r"(a[3]), "r"(b[0]), "r"(b[1]));
}

__device__ __forceinline__ void ldm_x4(uint32_t* r, uint32_t addr) {
    asm volatile("ldmatrix.sync.aligned.m8n8.x4.shared.b16 {%0,%1,%2,%3}, [%4];"
                 : "=r"(r[0]), "=r"(r[1]), "=r"(r[2]), "=r"(r[3]) : "r"(addr));
}
__device__ __forceinline__ void ldm_x4t(uint32_t* r, uint32_t addr) {
    asm volatile("ldmatrix.sync.aligned.m8n8.x4.trans.shared.b16 {%0,%1,%2,%3}, [%4];"
                 : "=r"(r[0]), "=r"(r[1]), "=r"(r[2]), "=r"(r[3]) : "r"(addr));
}
__device__ __forceinline__ void ldm_x2(uint32_t* r, uint32_t addr) {
    asm volatile("ldmatrix.sync.aligned.m8n8.x2.shared.b16 {%0,%1}, [%2];"
                 : "=r"(r[0]), "=r"(r[1]) : "r"(addr));
}
__device__ __forceinline__ void ldm_x2t(uint32_t* r, uint32_t addr) {
    asm volatile("ldmatrix.sync.aligned.m8n8.x2.trans.shared.b16 {%0,%1}, [%2];"
                 : "=r"(r[0]), "=r"(r[1]) : "r"(addr));
}

__device__ __forceinline__ void cp16(uint32_t dst, const void* src) {
    asm volatile("cp.async.cg.shared.global [%0], [%1], 16;" :: "r"(dst), "l"(src));
}
__device__ __forceinline__ void cp_commit() {
    asm volatile("cp.async.commit_group;" ::: "memory");
}
__device__ __forceinline__ void cp_wait1() {
    asm volatile("cp.async.wait_group 1;" ::: "memory");
}
__device__ __forceinline__ void cp_wait0() {
    asm volatile("cp.async.wait_group 0;" ::: "memory");
}

// ---------------------------------------------------------------------------
// Phase 1 (fp16 mma + cp.async pipeline, 1 sync/tile, self-thread-only deps):
//   g_part[bh][chunk][m][d] = sum_n V'[n][m]*Kf[n][d]
// grid (BH, NCH=32), block 320 (10 warps: mg = w>>1, dg = w&1)
// ---------------------------------------------------------------------------
__global__ __launch_bounds__(320, 4) void phase1_kernel(
    const float* __restrict__ Kg,
    const float* __restrict__ Vg,
    const float* __restrict__ maskg)
{
    __shared__ __align__(16) float KstF[2][T1][DD];
    __shared__ __align__(16) float VstF[2][T1][DD];
    __shared__ __half Ks[2][T1][S1K];
    __shared__ __half Vs[2][T1][S1V];

    const int bh = blockIdx.x, b = bh >> 3, h = bh & 7;
    const int chunk = blockIdx.y;
    const int t = threadIdx.x;
    const int w = t >> 5, lane = t & 31, q = lane & 3;
    const int g = lane >> 2, lr = lane & 7, sel = lane >> 3;
    const int mg = w >> 1, dg = w & 1;
    const int mrow = mg * 16;
    const int dcol = dg * 32;

    if (t < 64) {
        int bu = t >> 5, r = t & 31;
        Vs[bu][r][64] = __float2half(1.f);
        #pragma unroll
        for (int e = 65; e < 80; ++e) Vs[bu][r][e] = __float2half(0.f);
    }

    const size_t base = (size_t)b * NN * RS + (size_t)h * DD;
    const int n_beg = chunk * P1_CHUNK;
    const int NT = P1_CHUNK / T1;   // 8

    const bool loader = t < 256;
    const int r_ = (t & 255) >> 4, c_ = (t & 15) * 4;

    const float* kp = Kg + base + (size_t)(n_beg + r_) * RS + c_;
    const float* vp = Vg + base + (size_t)(n_beg + r_) * RS + c_;
    const float* mp = maskg + b * NN + n_beg + r_;

    const uint32_t kstb = smem_u32(&KstF[0][0][0]);
    const uint32_t vstb = smem_u32(&VstF[0][0][0]);

    const uint32_t ksb = smem_u32(&Ks[0][0][0]);
    const uint32_t vsb = smem_u32(&Vs[0][0][0]);
    const uint32_t aA = vsb + (((lr + (sel >> 1) * 8) * S1V) + mrow + (sel & 1) * 8) * 2;
    const uint32_t aB = ksb + (((lr + (sel & 1) * 8) * S1K) + dcol) * 2;
    const uint32_t BUFK = T1 * S1K * 2;
    const uint32_t BUFV = T1 * S1V * 2;

    float mreg[2][2];

    auto issue = [&](int tl, int s) {
        const int goff = tl * T1 * RS;
        if (loader) {
            const uint32_t d0 = kstb + ((s * T1 + r_) * DD + c_) * 4;
            const uint32_t d1 = vstb + ((s * T1 + r_) * DD + c_) * 4;
            cp16(d0,                kp + goff);
            cp16(d0 + 16 * DD * 4,  kp + goff + 16 * RS);
            cp16(d1,                vp + goff);
            cp16(d1 + 16 * DD * 4,  vp + goff + 16 * RS);
            mreg[s][0] = __ldg(mp + tl * T1);
            mreg[s][1] = __ldg(mp + tl * T1 + 16);
        }
    };

    float acc[4][4] = {};

    issue(0, 0); cp_commit();
    issue(1, 1); cp_commit();

    for (int tile = 0; tile < NT; ++tile) {
        const int s = tile & 1;
        cp_wait1();

        if (loader) {
            #pragma unroll
            for (int i = 0; i < 2; ++i) {
                int r = r_ + i * 16;
                float msk = mreg[s][i];
                float4 k4 = *(const float4*)&KstF[s][r][c_];
                float4 v4 = *(const float4*)&VstF[s][r][c_];
                *(__half2*)&Ks[s][r][c_]     = __floats2half2_rn(elu1(k4.x) * msk, elu1(k4.y) * msk);
                *(__half2*)&Ks[s][r][c_ + 2] = __floats2half2_rn(elu1(k4.z) * msk, elu1(k4.w) * msk);
                *(__half2*)&Vs[s][r][c_]     = __floats2half2_rn(v4.x, v4.y);
                *(__half2*)&Vs[s][r][c_ + 2] = __floats2half2_rn(v4.z, v4.w);
            }
        }
        __syncthreads();

        if (tile + 2 < NT) issue(tile + 2, s);
        cp_commit();

        #pragma unroll
        for (int kt = 0; kt < 2; ++kt) {
            uint32_t a[4];
            ldm_x4t(a, aA + s * BUFV + kt * 16 * S1V * 2);
            #pragma unroll
            for (int j = 0; j < 4; ++j) {
                uint32_t bf[2];
                ldm_x2t(bf, aB + s * BUFK + (kt * 16 * S1K + j * 8) * 2);
                mma16(acc[j], a, bf);
            }
        }
    }

    float* dst = &g_part[bh][chunk][0][0];
    #pragma unroll
    for (int j = 0; j < 4; ++j) {
        const int col = dcol + j * 8 + 2 * q;
        *(float2*)(dst + (mrow + g) * DD + col) = make_float2(acc[j][0], acc[j][1]);
        if (mg < 4)
            *(float2*)(dst + (mrow + 8 + g) * DD + col) = make_float2(acc[j][2], acc[j][3]);
    }
}

// ---------------------------------------------------------------------------
// Reduce: g_KVh[bh][r][c] = (half) sum_chunks g_part[bh][chunk][r][c]
// ---------------------------------------------------------------------------
__global__ __launch_bounds__(256) void reduce_kernel() {
    const int bh = blockIdx.x;
    const int e = blockIdx.y * 512 + threadIdx.x * 2;
    const int row = e >> 6, col = e & 63;
    float sx = 0.f, sy = 0.f;
    #pragma unroll 8
    for (int c = 0; c < NCH; ++c) {
        float2 v = *(const float2*)&g_part[bh][c][row][col];
        sx += v.x; sy += v.y;
    }
    *(__half2*)&g_KVh[bh][row][col] = __floats2half2_rn(sx, sy);
}

// ---------------------------------------------------------------------------
// Phase 2 (fp16 mma): out[n,m] = (Qf[n,:].KV[m,:]) / (Qf[n,:].Ksum + eps)
// grid (BH, NN/T2=64), block 256; warp w: rows w*16..+15
// Streaming hints: Q read-once (ldcs), out write-once (stcs).
// ---------------------------------------------------------------------------
__global__ __launch_bounds__(256) void phase2_kernel(
    const float* __restrict__ Qg,
    float* __restrict__ Og)
{
    __shared__ __half Qs[T2][S2H];
    __shared__ __align__(16) __half KVs[72][S2H];

    const int bh = blockIdx.x, b = bh >> 3, h = bh & 7;
    const int t = threadIdx.x;
    const int w = t >> 5, lane = t & 31, q = lane & 3;
    const int g = lane >> 2, lr = lane & 7, sel = lane >> 3;
    const int r0 = w * 16;

    const size_t base = (size_t)b * NN * RS + (size_t)h * DD;
    const int n0 = blockIdx.y * T2;

    // 1) Q LDGs first (streaming)
    float4 q4[8];
    {
        const float* src = Qg + base + (size_t)n0 * RS;
        #pragma unroll
        for (int i = 0; i < 8; ++i) {
            int idx = t + i * 256;
            int r = idx >> 4, c = (idx & 15) * 4;
            q4[i] = __ldcs((const float4*)(src + (size_t)r * RS + c));
        }
    }

    // 2) KV fill via cp.async
    {
        const uint32_t kvb = smem_u32(&KVs[0][0]);
        const char* srcb = (const char*)&g_KVh[bh][0][0];
        for (int i = t; i < 72 * 8; i += 256) {
            int r = i >> 3, c = i & 7;
            cp16(kvb + (r * S2H + c * 8) * 2, srcb + (r * 64 + c * 8) * 2);
        }
        cp_commit();
    }

    // 3) Convert Q -> fp16 smem
    #pragma unroll
    for (int i = 0; i < 8; ++i) {
        int idx = t + i * 256;
        int r = idx >> 4, c = (idx & 15) * 4;
        *(__half2*)&Qs[r][c]     = __floats2half2_rn(elu1(q4[i].x), elu1(q4[i].y));
        *(__half2*)&Qs[r][c + 2] = __floats2half2_rn(elu1(q4[i].z), elu1(q4[i].w));
    }
    cp_wait0();
    __syncthreads();

    const uint32_t qsb = smem_u32(&Qs[0][0]);
    const uint32_t kvb = smem_u32(&KVs[0][0]);

    uint32_t a[4][4];
    #pragma unroll
    for (int kt = 0; kt < 4; ++kt) {
        int row = r0 + lr + (sel & 1) * 8;
        int col = kt * 16 + (sel & 2) * 4;
        ldm_x4(a[kt], qsb + (row * S2H + col) * 2);
    }

    float dacc[4] = {};
    #pragma unroll
    for (int kt = 0; kt < 4; ++kt) {
        uint32_t bf[2];
        int row = 64 + lr;
        int col = kt * 16 + (sel & 1) * 8;
        ldm_x2(bf, kvb + (row * S2H + col) * 2);
        mma16(dacc, a[kt], bf);
    }
    const int src = lane & ~3;
    float den0 = __shfl_sync(0xffffffffu, dacc[0], src);
    float den1 = __shfl_sync(0xffffffffu, dacc[2], src);
    float z0 = 1.f / (den0 + 1e-6f);
    float z1 = 1.f / (den1 + 1e-6f);

    float* row_a = Og + base + (size_t)(n0 + r0 + g) * RS;
    float* row_b = row_a + 8 * RS;

    #pragma unroll
    for (int j = 0; j < 8; ++j) {
        float acc[4] = {};
        #pragma unroll
        for (int kt = 0; kt < 4; ++kt) {
            uint32_t bf[2];
            int row = j * 8 + lr;
            int col = kt * 16 + (sel & 1) * 8;
            ldm_x2(bf, kvb + (row * S2H + col) * 2);
            mma16(acc, a[kt], bf);
        }
        const int col = j * 8 + 2 * q;
        __stcs((float2*)(row_a + col), make_float2(acc[0] * z0, acc[1] * z0));
        __stcs((float2*)(row_b + col), make_float2(acc[2] * z1, acc[3] * z1));
    }
}

extern "C" void kernel_launch(void* const* d_in, const int* in_sizes, int n_in,
                              void* d_out, int out_size) {
    const float* Q    = (const float*)d_in[0];
    const float* K    = (const float*)d_in[1];
    const float* V    = (const float*)d_in[2];
    const float* mask = (const float*)d_in[3];
    float* out = (float*)d_out;

    dim3 g1(BH, NCH);
    phase1_kernel<<<g1, 320>>>(K, V, mask);

    dim3 gr(BH, 9);
    reduce_kernel<<<gr, 256>>>();

    dim3 g2(BH, NN / T2);
    phase2_kernel<<<g2, 256>>>(Q, out);
}

// round 14
// speedup vs baseline: 1.2779x; 1.0214x over previous
#include <cuda_runtime.h>
#include <cuda_fp16.h>
#include <cstdint>

#define BB 4
#define NN 8192
#define HH 8
#define DD 64
#define BH 32
#define RS 512

#define P1_CHUNK 256
#define NCH (NN/P1_CHUNK)    // 32 chunks
#define T1 32
#define S1K 72
#define S1V 88

#define T2 128
#define S2H 72

__device__ __align__(16) __half g_part[BH][NCH][72][DD];   // fp16 partials
__device__ __align__(16) __half g_KVh[BH][72][DD];

__device__ __forceinline__ float elu1(float x) {
    return __expf(fminf(x, 0.f)) + fmaxf(x, 0.f);
}

__device__ __forceinline__ uint32_t smem_u32(const void* p) {
    uint32_t a;
    asm("{ .reg .u64 t; cvta.to.shared.u64 t, %1; cvt.u32.u64 %0, t; }" : "=r"(a) : "l"(p));
    return a;
}

__device__ __forceinline__ void mma16(float* c, const uint32_t* a, const uint32_t* b) {
    asm volatile(
        "mma.sync.aligned.m16n8k16.row.col.f32.f16.f16.f32 "
        "{%0,%1,%2,%3}, {%4,%5,%6,%7}, {%8,%9}, {%0,%1,%2,%3};"
        : "+f"(c[0]), "+f"(c[1]), "+f"(c[2]), "+f"(c[3])
        : "r"(a[0]), "r"(a[1]), "r"(a[2]), "r"(a[3]), "r"(b[0]), "r"(b[1]));
}

__device__ __forceinline__ void ldm_x4(uint32_t* r, uint32_t addr) {
    asm volatile("ldmatrix.sync.aligned.m8n8.x4.shared.b16 {%0,%1,%2,%3}, [%4];"
                 : "=r"(r[0]), "=r"(r[1]), "=r"(r[2]), "=r"(r[3]) : "r"(addr));
}
__device__ __forceinline__ void ldm_x4t(uint32_t* r, uint32_t addr) {
    asm volatile("ldmatrix.sync.aligned.m8n8.x4.trans.shared.b16 {%0,%1,%2,%3}, [%4];"
                 : "=r"(r[0]), "=r"(r[1]), "=r"(r[2]), "=r"(r[3]) : "r"(addr));
}
__device__ __forceinline__ void ldm_x2(uint32_t* r, uint32_t addr) {
    asm volatile("ldmatrix.sync.aligned.m8n8.x2.shared.b16 {%0,%1}, [%2];"
                 : "=r"(r[0]), "=r"(r[1]) : "r"(addr));
}
__device__ __forceinline__ void ldm_x2t(uint32_t* r, uint32_t addr) {
    asm volatile("ldmatrix.sync.aligned.m8n8.x2.trans.shared.b16 {%0,%1}, [%2];"
                 : "=r"(r[0]), "=r"(r[1]) : "r"(addr));
}

__device__ __forceinline__ void cp16(uint32_t dst, const void* src) {
    asm volatile("cp.async.cg.shared.global [%0], [%1], 16;" :: "r"(dst), "l"(src));
}
__device__ __forceinline__ void cp_commit() {
    asm volatile("cp.async.commit_group;" ::: "memory");
}
__device__ __forceinline__ void cp_wait1() {
    asm volatile("cp.async.wait_group 1;" ::: "memory");
}
__device__ __forceinline__ void cp_wait0() {
    asm volatile("cp.async.wait_group 0;" ::: "memory");
}

// ---------------------------------------------------------------------------
// Phase 1 (fp16 mma + cp.async pipeline, 1 sync/tile, self-thread-only deps):
//   g_part[bh][chunk][m][d] = (half) sum_n V'[n][m]*Kf[n][d]
// grid (BH, NCH=32), block 320 (10 warps: mg = w>>1, dg = w&1)
// ---------------------------------------------------------------------------
__global__ __launch_bounds__(320, 4) void phase1_kernel(
    const float* __restrict__ Kg,
    const float* __restrict__ Vg,
    const float* __restrict__ maskg)
{
    __shared__ __align__(16) float KstF[2][T1][DD];
    __shared__ __align__(16) float VstF[2][T1][DD];
    __shared__ __half Ks[2][T1][S1K];
    __shared__ __half Vs[2][T1][S1V];

    const int bh = blockIdx.x, b = bh >> 3, h = bh & 7;
    const int chunk = blockIdx.y;
    const int t = threadIdx.x;
    const int w = t >> 5, lane = t & 31, q = lane & 3;
    const int g = lane >> 2, lr = lane & 7, sel = lane >> 3;
    const int mg = w >> 1, dg = w & 1;
    const int mrow = mg * 16;
    const int dcol = dg * 32;

    if (t < 64) {
        int bu = t >> 5, r = t & 31;
        Vs[bu][r][64] = __float2half(1.f);
        #pragma unroll
        for (int e = 65; e < 80; ++e) Vs[bu][r][e] = __float2half(0.f);
    }

    const size_t base = (size_t)b * NN * RS + (size_t)h * DD;
    const int n_beg = chunk * P1_CHUNK;
    const int NT = P1_CHUNK / T1;   // 8

    const bool loader = t < 256;
    const int r_ = (t & 255) >> 4, c_ = (t & 15) * 4;

    const float* kp = Kg + base + (size_t)(n_beg + r_) * RS + c_;
    const float* vp = Vg + base + (size_t)(n_beg + r_) * RS + c_;
    const float* mp = maskg + b * NN + n_beg + r_;

    const uint32_t kstb = smem_u32(&KstF[0][0][0]);
    const uint32_t vstb = smem_u32(&VstF[0][0][0]);

    const uint32_t ksb = smem_u32(&Ks[0][0][0]);
    const uint32_t vsb = smem_u32(&Vs[0][0][0]);
    const uint32_t aA = vsb + (((lr + (sel >> 1) * 8) * S1V) + mrow + (sel & 1) * 8) * 2;
    const uint32_t aB = ksb + (((lr + (sel & 1) * 8) * S1K) + dcol) * 2;
    const uint32_t BUFK = T1 * S1K * 2;
    const uint32_t BUFV = T1 * S1V * 2;

    float mreg[2][2];

    auto issue = [&](int tl, int s) {
        const int goff = tl * T1 * RS;
        if (loader) {
            const uint32_t d0 = kstb + ((s * T1 + r_) * DD + c_) * 4;
            const uint32_t d1 = vstb + ((s * T1 + r_) * DD + c_) * 4;
            cp16(d0,                kp + goff);
            cp16(d0 + 16 * DD * 4,  kp + goff + 16 * RS);
            cp16(d1,                vp + goff);
            cp16(d1 + 16 * DD * 4,  vp + goff + 16 * RS);
            mreg[s][0] = __ldg(mp + tl * T1);
            mreg[s][1] = __ldg(mp + tl * T1 + 16);
        }
    };

    float acc[4][4] = {};

    issue(0, 0); cp_commit();
    issue(1, 1); cp_commit();

    for (int tile = 0; tile < NT; ++tile) {
        const int s = tile & 1;
        cp_wait1();

        if (loader) {
            #pragma unroll
            for (int i = 0; i < 2; ++i) {
                int r = r_ + i * 16;
                float msk = mreg[s][i];
                float4 k4 = *(const float4*)&KstF[s][r][c_];
                float4 v4 = *(const float4*)&VstF[s][r][c_];
                *(__half2*)&Ks[s][r][c_]     = __floats2half2_rn(elu1(k4.x) * msk, elu1(k4.y) * msk);
                *(__half2*)&Ks[s][r][c_ + 2] = __floats2half2_rn(elu1(k4.z) * msk, elu1(k4.w) * msk);
                *(__half2*)&Vs[s][r][c_]     = __floats2half2_rn(v4.x, v4.y);
                *(__half2*)&Vs[s][r][c_ + 2] = __floats2half2_rn(v4.z, v4.w);
            }
        }
        __syncthreads();

        if (tile + 2 < NT) issue(tile + 2, s);
        cp_commit();

        #pragma unroll
        for (int kt = 0; kt < 2; ++kt) {
            uint32_t a[4];
            ldm_x4t(a, aA + s * BUFV + kt * 16 * S1V * 2);
            #pragma unroll
            for (int j = 0; j < 4; ++j) {
                uint32_t bf[2];
                ldm_x2t(bf, aB + s * BUFK + (kt * 16 * S1K + j * 8) * 2);
                mma16(acc[j], a, bf);
            }
        }
    }

    __half* dst = &g_part[bh][chunk][0][0];
    #pragma unroll
    for (int j = 0; j < 4; ++j) {
        const int col = dcol + j * 8 + 2 * q;
        *(__half2*)(dst + (mrow + g) * DD + col) = __floats2half2_rn(acc[j][0], acc[j][1]);
        if (mg < 4)
            *(__half2*)(dst + (mrow + 8 + g) * DD + col) = __floats2half2_rn(acc[j][2], acc[j][3]);
    }
}

// ---------------------------------------------------------------------------
// Reduce: g_KVh[bh][r][c] = (half) sum_chunks (float) g_part[bh][chunk][r][c]
// ---------------------------------------------------------------------------
__global__ __launch_bounds__(256) void reduce_kernel() {
    const int bh = blockIdx.x;
    const int e = blockIdx.y * 512 + threadIdx.x * 2;
    const int row = e >> 6, col = e & 63;
    float sx = 0.f, sy = 0.f;
    #pragma unroll 8
    for (int c = 0; c < NCH; ++c) {
        float2 v = __half22float2(*(const __half2*)&g_part[bh][c][row][col]);
        sx += v.x; sy += v.y;
    }
    *(__half2*)&g_KVh[bh][row][col] = __floats2half2_rn(sx, sy);
}

// ---------------------------------------------------------------------------
// Phase 2 (fp16 mma): out[n,m] = (Qf[n,:].KV[m,:]) / (Qf[n,:].Ksum + eps)
// grid (BH, NN/T2=64), block 256; warp w: rows w*16..+15
// ---------------------------------------------------------------------------
__global__ __launch_bounds__(256) void phase2_kernel(
    const float* __restrict__ Qg,
    float* __restrict__ Og)
{
    __shared__ __half Qs[T2][S2H];
    __shared__ __align__(16) __half KVs[72][S2H];

    const int bh = blockIdx.x, b = bh >> 3, h = bh & 7;
    const int t = threadIdx.x;
    const int w = t >> 5, lane = t & 31, q = lane & 3;
    const int g = lane >> 2, lr = lane & 7, sel = lane >> 3;
    const int r0 = w * 16;

    const size_t base = (size_t)b * NN * RS + (size_t)h * DD;
    const int n0 = blockIdx.y * T2;

    float4 q4[8];
    {
        const float* src = Qg + base + (size_t)n0 * RS;
        #pragma unroll
        for (int i = 0; i < 8; ++i) {
            int idx = t + i * 256;
            int r = idx >> 4, c = (idx & 15) * 4;
            q4[i] = __ldcs((const float4*)(src + (size_t)r * RS + c));
        }
    }

    {
        const uint32_t kvb = smem_u32(&KVs[0][0]);
        const char* srcb = (const char*)&g_KVh[bh][0][0];
        for (int i = t; i < 72 * 8; i += 256) {
            int r = i >> 3, c = i & 7;
            cp16(kvb + (r * S2H + c * 8) * 2, srcb + (r * 64 + c * 8) * 2);
        }
        cp_commit();
    }

    #pragma unroll
    for (int i = 0; i < 8; ++i) {
        int idx = t + i * 256;
        int r = idx >> 4, c = (idx & 15) * 4;
        *(__half2*)&Qs[r][c]     = __floats2half2_rn(elu1(q4[i].x), elu1(q4[i].y));
        *(__half2*)&Qs[r][c + 2] = __floats2half2_rn(elu1(q4[i].z), elu1(q4[i].w));
    }
    cp_wait0();
    __syncthreads();

    const uint32_t qsb = smem_u32(&Qs[0][0]);
    const uint32_t kvb = smem_u32(&KVs[0][0]);

    uint32_t a[4][4];
    #pragma unroll
    for (int kt = 0; kt < 4; ++kt) {
        int row = r0 + lr + (sel & 1) * 8;
        int col = kt * 16 + (sel & 2) * 4;
        ldm_x4(a[kt], qsb + (row * S2H + col) * 2);
    }

    float dacc[4] = {};
    #pragma unroll
    for (int kt = 0; kt < 4; ++kt) {
        uint32_t bf[2];
        int row = 64 + lr;
        int col = kt * 16 + (sel & 1) * 8;
        ldm_x2(bf, kvb + (row * S2H + col) * 2);
        mma16(dacc, a[kt], bf);
    }
    const int src = lane & ~3;
    float den0 = __shfl_sync(0xffffffffu, dacc[0], src);
    float den1 = __shfl_sync(0xffffffffu, dacc[2], src);
    float z0 = 1.f / (den0 + 1e-6f);
    float z1 = 1.f / (den1 + 1e-6f);

    float* row_a = Og + base + (size_t)(n0 + r0 + g) * RS;
    float* row_b = row_a + 8 * RS;

    #pragma unroll
    for (int j = 0; j < 8; ++j) {
        float acc[4] = {};
        #pragma unroll
        for (int kt = 0; kt < 4; ++kt) {
            uint32_t bf[2];
            int row = j * 8 + lr;
            int col = kt * 16 + (sel & 1) * 8;
            ldm_x2(bf, kvb + (row * S2H + col) * 2);
            mma16(acc, a[kt], bf);
        }
        const int col = j * 8 + 2 * q;
        __stcs((float2*)(row_a + col), make_float2(acc[0] * z0, acc[1] * z0));
        __stcs((float2*)(row_b + col), make_float2(acc[2] * z1, acc[3] * z1));
    }
}

extern "C" void kernel_launch(void* const* d_in, const int* in_sizes, int n_in,
                              void* d_out, int out_size) {
    const float* Q    = (const float*)d_in[0];
    const float* K    = (const float*)d_in[1];
    const float* V    = (const float*)d_in[2];
    const float* mask = (const float*)d_in[3];
    float* out = (float*)d_out;

    dim3 g1(BH, NCH);
    phase1_kernel<<<g1, 320>>>(K, V, mask);

    dim3 gr(BH, 9);
    reduce_kernel<<<gr, 256>>>();

    dim3 g2(BH, NN / T2);
    phase2_kernel<<<g2, 256>>>(Q, out);
}